// round 1
// baseline (speedup 1.0000x reference)
#include <cuda_runtime.h>
#include <cstdint>
#include <cstddef>

// Problem constants
#define Bq   8
#define Cc   256
#define Hh   64
#define Ww   64
#define HWc  4096           // Hh*Ww
#define TOTAL (8UL*256*4096)

// ---------------- scratch (device globals; no allocation allowed) ------------
__device__ float g_fe [TOTAL];        // feature embedding (B,C,H,W)
__device__ float g_agg[TOTAL];        // aggregated features (B,C,H,W)
__device__ float g_enh[TOTAL];        // enhanced features  (B,C,H,W)
__device__ float g_w1f[256*256];      // BN-folded embed weight
__device__ float g_w2f[256*512];      // BN-folded enhance weight
__device__ float g_b1f[256];
__device__ float g_b2f[256];
__device__ float g_nrm[Bq*HWc];       // per-pixel L2 norm of fe over C
__device__ float g_pool[Bq*512];      // pooled (B, 2C)
__device__ float g_gate[Bq*256];      // sigmoid gate (B, C)

// ---------------- BN fold: W' = diag(g/sqrt(v+eps)) W ; b' = b*inv + beta - mean*inv
__global__ void fold_kernel(const float* __restrict__ w, const float* __restrict__ bsrc,
                            const float* __restrict__ gm, const float* __restrict__ bt,
                            const float* __restrict__ mn, const float* __restrict__ vr,
                            int cin, int which) {
    int o = blockIdx.x;
    float inv = gm[o] * rsqrtf(vr[o] + 1e-5f);
    float* wf = which ? g_w2f : g_w1f;
    float* bf = which ? g_b2f : g_b1f;
    for (int c = threadIdx.x; c < cin; c += blockDim.x)
        wf[o * cin + c] = inv * w[o * cin + c];
    if (threadIdx.x == 0)
        bf[o] = bsrc[o] * inv + bt[o] - mn[o] * inv;
}

// ---------------- GEMM + bias + relu -----------------------------------------
// out[b, m, n] = relu( sum_k A[m,k] * Bmat[b, k, n] + bias[m] )
// A: (256, CIN) row major (folded).  Bmat rows: phase 0 -> x ; phase 1 -> [x ; agg]
// Tiling: BM=BN=128, BK=8, 256 threads, 8x8 per-thread tile.
template <int CIN, int PHASE>
__global__ __launch_bounds__(256) void gemm_kernel(const float* __restrict__ xin) {
    __shared__ float sA[8][128];
    __shared__ float sB[8][128];

    const float* A    = (PHASE == 0) ? g_w1f : g_w2f;
    const float* bias = (PHASE == 0) ? g_b1f : g_b2f;
    float*       out  = (PHASE == 0) ? g_fe  : g_enh;

    const int bb = blockIdx.z;
    const int n0 = blockIdx.x * 128;
    const int m0 = blockIdx.y * 128;
    const int tid = threadIdx.x;
    const int tx = tid & 15;        // n group
    const int ty = tid >> 4;        // m group

    const float* xb = xin + (size_t)bb * Cc * HWc;

    const int mA = tid >> 1;
    const int kqA = (tid & 1) * 4;
    const int kB = tid >> 5;
    const int nB = (tid & 31) * 4;

    float acc[8][8];
#pragma unroll
    for (int i = 0; i < 8; i++)
#pragma unroll
        for (int j = 0; j < 8; j++) acc[i][j] = 0.f;

    for (int k0 = 0; k0 < CIN; k0 += 8) {
        float4 av = *(const float4*)&A[(size_t)(m0 + mA) * CIN + k0 + kqA];
        int kk = k0 + kB;
        const float* brow;
        if (PHASE == 0) {
            brow = xb + (size_t)kk * HWc;
        } else {
            brow = (kk < Cc) ? (xb + (size_t)kk * HWc)
                             : (g_agg + ((size_t)bb * Cc + (kk - Cc)) * HWc);
        }
        float4 bv = *(const float4*)&brow[n0 + nB];

        __syncthreads();
        sA[kqA + 0][mA] = av.x;
        sA[kqA + 1][mA] = av.y;
        sA[kqA + 2][mA] = av.z;
        sA[kqA + 3][mA] = av.w;
        *(float4*)&sB[kB][nB] = bv;
        __syncthreads();

#pragma unroll
        for (int k = 0; k < 8; k++) {
            float4 a0 = *(const float4*)&sA[k][ty * 8];
            float4 a1 = *(const float4*)&sA[k][ty * 8 + 4];
            float4 b0 = *(const float4*)&sB[k][tx * 8];
            float4 b1 = *(const float4*)&sB[k][tx * 8 + 4];
            float ar[8] = {a0.x, a0.y, a0.z, a0.w, a1.x, a1.y, a1.z, a1.w};
            float br[8] = {b0.x, b0.y, b0.z, b0.w, b1.x, b1.y, b1.z, b1.w};
#pragma unroll
            for (int i = 0; i < 8; i++)
#pragma unroll
                for (int j = 0; j < 8; j++)
                    acc[i][j] += ar[i] * br[j];
        }
    }

#pragma unroll
    for (int i = 0; i < 8; i++) {
        int m = m0 + ty * 8 + i;
        float bs = bias[m];
        float4 v0, v1;
        v0.x = fmaxf(acc[i][0] + bs, 0.f);
        v0.y = fmaxf(acc[i][1] + bs, 0.f);
        v0.z = fmaxf(acc[i][2] + bs, 0.f);
        v0.w = fmaxf(acc[i][3] + bs, 0.f);
        v1.x = fmaxf(acc[i][4] + bs, 0.f);
        v1.y = fmaxf(acc[i][5] + bs, 0.f);
        v1.z = fmaxf(acc[i][6] + bs, 0.f);
        v1.w = fmaxf(acc[i][7] + bs, 0.f);
        float* orow = out + ((size_t)bb * Cc + m) * HWc + n0 + tx * 8;
        *(float4*)&orow[0] = v0;
        *(float4*)&orow[4] = v1;
    }
}

// ---------------- per-pixel L2 norm of fe over channels ----------------------
__global__ void norm_kernel() {
    int idx = blockIdx.x * blockDim.x + threadIdx.x;   // [0, B*HW)
    int b = idx >> 12;        // / 4096
    int hw = idx & 4095;
    const float* p = g_fe + (size_t)b * Cc * HWc + hw;
    float s = 0.f;
#pragma unroll 8
    for (int c = 0; c < Cc; c++) {
        float v = p[(size_t)c * HWc];
        s += v * v;
    }
    g_nrm[idx] = sqrtf(s);
}

// ---------------- cosine sim + softmax + dynamic aggregation -----------------
#define TILE 16
#define HALO 18
#define CKC  16
__global__ __launch_bounds__(256) void simagg_kernel(const float* __restrict__ xin) {
    __shared__ float sh[CKC][HALO * HALO];   // 20736 B

    const int b = blockIdx.z;
    const int h0 = blockIdx.y * TILE;
    const int w0 = blockIdx.x * TILE;
    const int lx = threadIdx.x & (TILE - 1);
    const int ly = threadIdx.x / TILE;
    const int h = h0 + ly, w = w0 + lx;

    const float* feb = g_fe + (size_t)b * Cc * HWc;
    const float* xb  = xin  + (size_t)b * Cc * HWc;

    float dot[9];
#pragma unroll
    for (int k = 0; k < 9; k++) dot[k] = 0.f;

    // pass 1: accumulate 9 dot products over all channels
    for (int cc = 0; cc < Cc; cc += CKC) {
        for (int idx = threadIdx.x; idx < CKC * HALO * HALO; idx += 256) {
            int c = idx / (HALO * HALO);
            int p = idx - c * (HALO * HALO);
            int hy = p / HALO, hx = p - hy * HALO;
            int gh = h0 + hy - 1, gw = w0 + hx - 1;
            float v = 0.f;
            if (gh >= 0 && gh < Hh && gw >= 0 && gw < Ww)
                v = feb[(size_t)(cc + c) * HWc + gh * Ww + gw];
            sh[c][p] = v;
        }
        __syncthreads();
#pragma unroll 4
        for (int c = 0; c < CKC; c++) {
            float ctr = sh[c][(ly + 1) * HALO + (lx + 1)];
#pragma unroll
            for (int di = 0; di < 3; di++)
#pragma unroll
                for (int dj = 0; dj < 3; dj++)
                    dot[di * 3 + dj] += ctr * sh[c][(ly + di) * HALO + (lx + dj)];
        }
        __syncthreads();
    }

    // cosine + softmax over the 9-window
    float nc = g_nrm[b * HWc + h * Ww + w];
    float s[9];
#pragma unroll
    for (int k = 0; k < 9; k++) {
        int di = k / 3, dj = k - 3 * di;
        int nh = h + di - 1, nw = w + dj - 1;
        float np = (nh >= 0 && nh < Hh && nw >= 0 && nw < Ww)
                       ? g_nrm[b * HWc + nh * Ww + nw] : 0.f;
        s[k] = dot[k] / (nc * np + 1e-7f);
    }
    float mx = s[0];
#pragma unroll
    for (int k = 1; k < 9; k++) mx = fmaxf(mx, s[k]);
    float sum = 0.f;
#pragma unroll
    for (int k = 0; k < 9; k++) { s[k] = expf(s[k] - mx); sum += s[k]; }
    float inv = 1.f / sum;
#pragma unroll
    for (int k = 0; k < 9; k++) s[k] *= inv;

    // pass 2: weighted 3x3 gather on original x
    for (int cc = 0; cc < Cc; cc += CKC) {
        for (int idx = threadIdx.x; idx < CKC * HALO * HALO; idx += 256) {
            int c = idx / (HALO * HALO);
            int p = idx - c * (HALO * HALO);
            int hy = p / HALO, hx = p - hy * HALO;
            int gh = h0 + hy - 1, gw = w0 + hx - 1;
            float v = 0.f;
            if (gh >= 0 && gh < Hh && gw >= 0 && gw < Ww)
                v = xb[(size_t)(cc + c) * HWc + gh * Ww + gw];
            sh[c][p] = v;
        }
        __syncthreads();
#pragma unroll 4
        for (int c = 0; c < CKC; c++) {
            float a = 0.f;
#pragma unroll
            for (int di = 0; di < 3; di++)
#pragma unroll
                for (int dj = 0; dj < 3; dj++)
                    a += s[di * 3 + dj] * sh[c][(ly + di) * HALO + (lx + dj)];
            g_agg[((size_t)b * Cc + cc + c) * HWc + h * Ww + w] = a;
        }
        __syncthreads();
    }
}

// ---------------- global average pool over HW of [x ; enhanced] --------------
__global__ void pool_kernel(const float* __restrict__ xin) {
    const int c2 = blockIdx.x;     // [0, 512)
    const int b = blockIdx.y;
    const int tid = threadIdx.x;
    const float* src = (c2 < Cc) ? (xin  + ((size_t)b * Cc + c2) * HWc)
                                 : (g_enh + ((size_t)b * Cc + (c2 - Cc)) * HWc);
    float s = 0.f;
    for (int i = tid * 4; i < HWc; i += 1024) {
        float4 v = *(const float4*)&src[i];
        s += v.x + v.y + v.z + v.w;
    }
#pragma unroll
    for (int o = 16; o > 0; o >>= 1) s += __shfl_down_sync(0xffffffffu, s, o);
    __shared__ float red[8];
    if ((tid & 31) == 0) red[tid >> 5] = s;
    __syncthreads();
    if (tid < 8) {
        float t = red[tid];
#pragma unroll
        for (int o = 4; o > 0; o >>= 1) t += __shfl_down_sync(0xffu, t, o);
        if (tid == 0) g_pool[b * 512 + c2] = t * (1.f / HWc);
    }
}

// ---------------- SE gate: relu(W1 p + b1) -> sigmoid(W2 h + b2) -------------
__global__ void gate_kernel(const float* __restrict__ w1, const float* __restrict__ b1,
                            const float* __restrict__ w2, const float* __restrict__ b2) {
    const int b = blockIdx.x;
    const int tid = threadIdx.x;
    __shared__ float sp[512];
    __shared__ float shid[64];
    for (int i = tid; i < 512; i += 256) sp[i] = g_pool[b * 512 + i];
    __syncthreads();
    if (tid < 64) {
        float s = b1[tid];
        const float* wr = w1 + tid * 512;
#pragma unroll 8
        for (int c = 0; c < 512; c++) s += wr[c] * sp[c];
        shid[tid] = fmaxf(s, 0.f);
    }
    __syncthreads();
    float s = b2[tid];
    const float* wr = w2 + tid * 64;
#pragma unroll
    for (int j = 0; j < 64; j++) s += wr[j] * shid[j];
    g_gate[b * 256 + tid] = 1.f / (1.f + expf(-s));
}

// ---------------- residual + gated enhancement -------------------------------
__global__ void final_kernel(const float* __restrict__ xin, float* __restrict__ out) {
    size_t e = ((size_t)blockIdx.x * blockDim.x + threadIdx.x) * 4;
    if (e >= TOTAL) return;
    int bc = (int)(e >> 12);           // e / 4096 = b*256 + c
    float g = g_gate[bc];
    float4 xv = *(const float4*)&xin[e];
    float4 ev = *(const float4*)&g_enh[e];
    float4 o;
    o.x = xv.x + g * ev.x;
    o.y = xv.y + g * ev.y;
    o.z = xv.z + g * ev.z;
    o.w = xv.w + g * ev.w;
    *(float4*)&out[e] = o;
}

// ---------------- launch ------------------------------------------------------
extern "C" void kernel_launch(void* const* d_in, const int* in_sizes, int n_in,
                              void* d_out, int out_size) {
    const float* x       = (const float*)d_in[0];
    const float* w_embed = (const float*)d_in[1];
    const float* b_embed = (const float*)d_in[2];
    const float* bn1_g   = (const float*)d_in[3];
    const float* bn1_b   = (const float*)d_in[4];
    const float* bn1_m   = (const float*)d_in[5];
    const float* bn1_v   = (const float*)d_in[6];
    const float* w_enh   = (const float*)d_in[7];
    const float* b_enh   = (const float*)d_in[8];
    const float* bn2_g   = (const float*)d_in[9];
    const float* bn2_b   = (const float*)d_in[10];
    const float* bn2_m   = (const float*)d_in[11];
    const float* bn2_v   = (const float*)d_in[12];
    const float* w_g1    = (const float*)d_in[13];
    const float* b_g1    = (const float*)d_in[14];
    const float* w_g2    = (const float*)d_in[15];
    const float* b_g2    = (const float*)d_in[16];
    float* out = (float*)d_out;

    fold_kernel<<<256, 256>>>(w_embed, b_embed, bn1_g, bn1_b, bn1_m, bn1_v, 256, 0);
    fold_kernel<<<256, 256>>>(w_enh,   b_enh,   bn2_g, bn2_b, bn2_m, bn2_v, 512, 1);

    gemm_kernel<256, 0><<<dim3(HWc / 128, 2, Bq), 256>>>(x);      // fe
    norm_kernel<<<(Bq * HWc) / 256, 256>>>();
    simagg_kernel<<<dim3(Ww / TILE, Hh / TILE, Bq), 256>>>(x);    // agg
    gemm_kernel<512, 1><<<dim3(HWc / 128, 2, Bq), 256>>>(x);      // enhanced

    pool_kernel<<<dim3(512, Bq), 256>>>(x);
    gate_kernel<<<Bq, 256>>>(w_g1, b_g1, w_g2, b_g2);
    final_kernel<<<(unsigned)(TOTAL / 4 / 256), 256>>>(x, out);
}

// round 3
// speedup vs baseline: 1.7909x; 1.7909x over previous
#include <cuda_runtime.h>
#include <cstdint>
#include <cstddef>

// Problem constants
#define Bq   8
#define Cc   256
#define Hh   64
#define Ww   64
#define HWc  4096
#define TOTAL (8UL*256*4096)

// ---------------- scratch (device globals) ------------------------------------
__device__ float g_fe [TOTAL];
__device__ float g_agg[TOTAL];
__device__ float g_enh[TOTAL];
__device__ float g_w1f[256*256];
__device__ float g_w2f[256*512];
__device__ float g_b1f[256];
__device__ float g_b2f[256];
__device__ float g_nrm [Bq*HWc];
__device__ float g_nrmp[4*Bq*HWc];
__device__ float g_pool[Bq*512];
__device__ float g_gate[Bq*256];

// ---------------- BN fold ------------------------------------------------------
__global__ void fold_kernel(const float* __restrict__ w, const float* __restrict__ bsrc,
                            const float* __restrict__ gm, const float* __restrict__ bt,
                            const float* __restrict__ mn, const float* __restrict__ vr,
                            int cin, int which) {
    int o = blockIdx.x;
    float inv = gm[o] * rsqrtf(vr[o] + 1e-5f);
    float* wf = which ? g_w2f : g_w1f;
    float* bf = which ? g_b2f : g_b1f;
    for (int c = threadIdx.x; c < cin; c += blockDim.x)
        wf[o * cin + c] = inv * w[o * cin + c];
    if (threadIdx.x == 0)
        bf[o] = bsrc[o] * inv + bt[o] - mn[o] * inv;
}

// ---------------- mma.sync tf32 GEMM + bias + relu ------------------------------
// out[b, m, n] = relu( sum_k A[m,k] * B[k,n] + bias[m] ),  n = pixel index
// A: folded weight [256, CIN] row-major.  B rows: x / [x ; agg], [CIN, 4096].
// CTA: 128x128 tile, 8 warps (warp tile 64x32), BK=16, cp.async double buffer.
#define BK   16
#define PADA 20     // floats per A smem row (16 data + 4 pad): conflict-free frags
#define PADB 136    // floats per B smem row (128 data + 8 pad)

__device__ __forceinline__ void mma_tf32(float c[4], const uint32_t a[4], const uint32_t b[2]) {
    asm volatile(
        "mma.sync.aligned.m16n8k8.row.col.f32.tf32.tf32.f32 "
        "{%0,%1,%2,%3}, {%4,%5,%6,%7}, {%8,%9}, {%0,%1,%2,%3};"
        : "+f"(c[0]), "+f"(c[1]), "+f"(c[2]), "+f"(c[3])
        : "r"(a[0]), "r"(a[1]), "r"(a[2]), "r"(a[3]), "r"(b[0]), "r"(b[1]));
}

template <int CIN, int PHASE>
__global__ __launch_bounds__(256) void mma_gemm(const float* __restrict__ xin) {
    __shared__ float sA[2][128 * PADA];
    __shared__ float sB[2][BK * PADB];

    const int tid  = threadIdx.x;
    const int wid  = tid >> 5;
    const int lane = tid & 31;
    const int wm = wid >> 2;          // 0..1  (m warp)
    const int wn = wid & 3;           // 0..3  (n warp)
    const int gq = lane >> 2;         // group 0..7
    const int tg = lane & 3;          // 0..3

    const int bb = blockIdx.z;
    const int n0 = blockIdx.x * 128;
    const int m0 = blockIdx.y * 128;

    const float* Aw   = PHASE ? g_w2f : g_w1f;
    const float* bias = PHASE ? g_b2f : g_b1f;
    float*       out  = PHASE ? g_enh : g_fe;
    const float* xb   = xin  + (size_t)bb * Cc * HWc;
    const float* aggb = g_agg + (size_t)bb * Cc * HWc;

    uint32_t sAa, sBa;
    asm("{ .reg .u64 t; cvta.to.shared.u64 t, %1; cvt.u32.u64 %0, t; }" : "=r"(sAa) : "l"(&sA[0][0]));
    asm("{ .reg .u64 t; cvta.to.shared.u64 t, %1; cvt.u32.u64 %0, t; }" : "=r"(sBa) : "l"(&sB[0][0]));

    auto fill = [&](int ci) {
        const int buf = ci & 1;
        const int k0 = ci * BK;
        const uint32_t sAb = sAa + buf * (128 * PADA * 4);
        const uint32_t sBb = sBa + buf * (BK * PADB * 4);
#pragma unroll
        for (int it = 0; it < 2; it++) {          // A: 512 x 16B chunks
            int id = it * 256 + tid;
            int r = id >> 2, q = id & 3;
            const float* gp = &Aw[(size_t)(m0 + r) * CIN + k0 + q * 4];
            uint32_t s = sAb + (uint32_t)(r * PADA + q * 4) * 4;
            asm volatile("cp.async.cg.shared.global [%0], [%1], 16;" :: "r"(s), "l"(gp));
        }
#pragma unroll
        for (int it = 0; it < 2; it++) {          // B: 512 x 16B chunks
            int id = it * 256 + tid;
            int kr = id >> 5, q = id & 31;
            int kg = k0 + kr;
            const float* brow;
            if (PHASE == 0) brow = xb + (size_t)kg * HWc;
            else            brow = (kg < Cc) ? xb + (size_t)kg * HWc
                                             : aggb + (size_t)(kg - Cc) * HWc;
            const float* gp = &brow[n0 + q * 4];
            uint32_t s = sBb + (uint32_t)(kr * PADB + q * 4) * 4;
            asm volatile("cp.async.cg.shared.global [%0], [%1], 16;" :: "r"(s), "l"(gp));
        }
        asm volatile("cp.async.commit_group;" ::: "memory");
    };

    float acc[4][4][4];
#pragma unroll
    for (int mt = 0; mt < 4; mt++)
#pragma unroll
        for (int nt = 0; nt < 4; nt++)
#pragma unroll
            for (int i = 0; i < 4; i++) acc[mt][nt][i] = 0.f;

    constexpr int NC = CIN / BK;
    fill(0);

    for (int ci = 0; ci < NC; ci++) {
        if (ci + 1 < NC) {
            fill(ci + 1);
            asm volatile("cp.async.wait_group 1;" ::: "memory");
        } else {
            asm volatile("cp.async.wait_group 0;" ::: "memory");
        }
        __syncthreads();

        const int buf = ci & 1;
        const float* A_ = sA[buf];
        const float* B_ = sB[buf];
#pragma unroll
        for (int k8 = 0; k8 < 2; k8++) {
            const int kb = k8 * 8;
            uint32_t afr[4][4];
#pragma unroll
            for (int mt = 0; mt < 4; mt++) {
                int row = wm * 64 + mt * 16 + gq;
                afr[mt][0] = __float_as_uint(A_[row * PADA + kb + tg]);
                afr[mt][1] = __float_as_uint(A_[(row + 8) * PADA + kb + tg]);
                afr[mt][2] = __float_as_uint(A_[row * PADA + kb + tg + 4]);
                afr[mt][3] = __float_as_uint(A_[(row + 8) * PADA + kb + tg + 4]);
            }
            uint32_t bfr[4][2];
#pragma unroll
            for (int nt = 0; nt < 4; nt++) {
                int col = wn * 32 + nt * 8 + gq;
                bfr[nt][0] = __float_as_uint(B_[(kb + tg) * PADB + col]);
                bfr[nt][1] = __float_as_uint(B_[(kb + 4 + tg) * PADB + col]);
            }
#pragma unroll
            for (int mt = 0; mt < 4; mt++)
#pragma unroll
                for (int nt = 0; nt < 4; nt++)
                    mma_tf32(acc[mt][nt], afr[mt], bfr[nt]);
        }
        __syncthreads();
    }

    // epilogue: bias + relu, float2 stores
#pragma unroll
    for (int mt = 0; mt < 4; mt++) {
        int row0 = m0 + wm * 64 + mt * 16 + gq;
        float bs0 = bias[row0];
        float bs1 = bias[row0 + 8];
        float* o0 = out + ((size_t)bb * Cc + row0) * HWc;
        float* o1 = o0 + 8 * HWc;
#pragma unroll
        for (int nt = 0; nt < 4; nt++) {
            int col = n0 + wn * 32 + nt * 8 + 2 * tg;
            float2 v0, v1;
            v0.x = fmaxf(acc[mt][nt][0] + bs0, 0.f);
            v0.y = fmaxf(acc[mt][nt][1] + bs0, 0.f);
            v1.x = fmaxf(acc[mt][nt][2] + bs1, 0.f);
            v1.y = fmaxf(acc[mt][nt][3] + bs1, 0.f);
            *(float2*)&o0[col] = v0;
            *(float2*)&o1[col] = v1;
        }
    }
}

// ---------------- norm: split 4-way (deterministic), then combine+sqrt ---------
__global__ void norm1_kernel() {
    int idx = blockIdx.x * blockDim.x + threadIdx.x;   // [0, 4*32768)
    int g = idx >> 15;
    int pix = idx & 32767;
    int b = pix >> 12, hw = pix & 4095;
    const float* p = g_fe + ((size_t)b * Cc + g * 64) * HWc + hw;
    float s = 0.f;
#pragma unroll 8
    for (int c = 0; c < 64; c++) {
        float v = p[(size_t)c * HWc];
        s += v * v;
    }
    g_nrmp[idx] = s;
}
__global__ void norm2_kernel() {
    int pix = blockIdx.x * blockDim.x + threadIdx.x;   // [0, 32768)
    g_nrm[pix] = sqrtf(g_nrmp[pix] + g_nrmp[32768 + pix] +
                       g_nrmp[65536 + pix] + g_nrmp[98304 + pix]);
}

// ---------------- cosine sim + softmax + dynamic aggregation -------------------
#define TILE 16
#define HALO 18
#define CKC  16
__global__ __launch_bounds__(256) void simagg_kernel(const float* __restrict__ xin) {
    __shared__ float sh[CKC][HALO * HALO];

    const int b = blockIdx.z;
    const int h0 = blockIdx.y * TILE;
    const int w0 = blockIdx.x * TILE;
    const int lx = threadIdx.x & (TILE - 1);
    const int ly = threadIdx.x / TILE;
    const int h = h0 + ly, w = w0 + lx;

    const float* feb = g_fe + (size_t)b * Cc * HWc;
    const float* xb  = xin  + (size_t)b * Cc * HWc;

    float dot[9];
#pragma unroll
    for (int k = 0; k < 9; k++) dot[k] = 0.f;

    for (int cc = 0; cc < Cc; cc += CKC) {
        for (int idx = threadIdx.x; idx < CKC * HALO * HALO; idx += 256) {
            int c = idx / (HALO * HALO);
            int p = idx - c * (HALO * HALO);
            int hy = p / HALO, hx = p - hy * HALO;
            int gh = h0 + hy - 1, gw = w0 + hx - 1;
            float v = 0.f;
            if (gh >= 0 && gh < Hh && gw >= 0 && gw < Ww)
                v = feb[(size_t)(cc + c) * HWc + gh * Ww + gw];
            sh[c][p] = v;
        }
        __syncthreads();
#pragma unroll 4
        for (int c = 0; c < CKC; c++) {
            float ctr = sh[c][(ly + 1) * HALO + (lx + 1)];
#pragma unroll
            for (int di = 0; di < 3; di++)
#pragma unroll
                for (int dj = 0; dj < 3; dj++)
                    dot[di * 3 + dj] += ctr * sh[c][(ly + di) * HALO + (lx + dj)];
        }
        __syncthreads();
    }

    float nc = g_nrm[b * HWc + h * Ww + w];
    float s[9];
#pragma unroll
    for (int k = 0; k < 9; k++) {
        int di = k / 3, dj = k - 3 * di;
        int nh = h + di - 1, nw = w + dj - 1;
        float np = (nh >= 0 && nh < Hh && nw >= 0 && nw < Ww)
                       ? g_nrm[b * HWc + nh * Ww + nw] : 0.f;
        s[k] = dot[k] / (nc * np + 1e-7f);
    }
    float mx = s[0];
#pragma unroll
    for (int k = 1; k < 9; k++) mx = fmaxf(mx, s[k]);
    float sum = 0.f;
#pragma unroll
    for (int k = 0; k < 9; k++) { s[k] = expf(s[k] - mx); sum += s[k]; }
    float inv = 1.f / sum;
#pragma unroll
    for (int k = 0; k < 9; k++) s[k] *= inv;

    for (int cc = 0; cc < Cc; cc += CKC) {
        for (int idx = threadIdx.x; idx < CKC * HALO * HALO; idx += 256) {
            int c = idx / (HALO * HALO);
            int p = idx - c * (HALO * HALO);
            int hy = p / HALO, hx = p - hy * HALO;
            int gh = h0 + hy - 1, gw = w0 + hx - 1;
            float v = 0.f;
            if (gh >= 0 && gh < Hh && gw >= 0 && gw < Ww)
                v = xb[(size_t)(cc + c) * HWc + gh * Ww + gw];
            sh[c][p] = v;
        }
        __syncthreads();
#pragma unroll 4
        for (int c = 0; c < CKC; c++) {
            float a = 0.f;
#pragma unroll
            for (int di = 0; di < 3; di++)
#pragma unroll
                for (int dj = 0; dj < 3; dj++)
                    a += s[di * 3 + dj] * sh[c][(ly + di) * HALO + (lx + dj)];
            g_agg[((size_t)b * Cc + cc + c) * HWc + h * Ww + w] = a;
        }
        __syncthreads();
    }
}

// ---------------- global average pool over HW of [x ; enhanced] ----------------
__global__ void pool_kernel(const float* __restrict__ xin) {
    const int c2 = blockIdx.x;
    const int b = blockIdx.y;
    const int tid = threadIdx.x;
    const float* src = (c2 < Cc) ? (xin   + ((size_t)b * Cc + c2) * HWc)
                                 : (g_enh + ((size_t)b * Cc + (c2 - Cc)) * HWc);
    float s = 0.f;
    for (int i = tid * 4; i < HWc; i += 1024) {
        float4 v = *(const float4*)&src[i];
        s += v.x + v.y + v.z + v.w;
    }
#pragma unroll
    for (int o = 16; o > 0; o >>= 1) s += __shfl_down_sync(0xffffffffu, s, o);
    __shared__ float red[8];
    if ((tid & 31) == 0) red[tid >> 5] = s;
    __syncthreads();
    if (tid < 8) {
        float t = red[tid];
#pragma unroll
        for (int o = 4; o > 0; o >>= 1) t += __shfl_down_sync(0xffu, t, o);
        if (tid == 0) g_pool[b * 512 + c2] = t * (1.f / HWc);
    }
}

// ---------------- SE gate --------------------------------------------------------
__global__ void gate_kernel(const float* __restrict__ w1, const float* __restrict__ b1,
                            const float* __restrict__ w2, const float* __restrict__ b2) {
    const int b = blockIdx.x;
    const int tid = threadIdx.x;
    __shared__ float sp[512];
    __shared__ float shid[64];
    for (int i = tid; i < 512; i += 256) sp[i] = g_pool[b * 512 + i];
    __syncthreads();
    if (tid < 64) {
        float s = b1[tid];
        const float* wr = w1 + tid * 512;
#pragma unroll 8
        for (int c = 0; c < 512; c++) s += wr[c] * sp[c];
        shid[tid] = fmaxf(s, 0.f);
    }
    __syncthreads();
    float s = b2[tid];
    const float* wr = w2 + tid * 64;
#pragma unroll
    for (int j = 0; j < 64; j++) s += wr[j] * shid[j];
    g_gate[b * 256 + tid] = 1.f / (1.f + expf(-s));
}

// ---------------- residual + gated enhancement ----------------------------------
__global__ void final_kernel(const float* __restrict__ xin, float* __restrict__ out) {
    size_t e = ((size_t)blockIdx.x * blockDim.x + threadIdx.x) * 4;
    if (e >= TOTAL) return;
    int bc = (int)(e >> 12);
    float g = g_gate[bc];
    float4 xv = *(const float4*)&xin[e];
    float4 ev = *(const float4*)&g_enh[e];
    float4 o;
    o.x = xv.x + g * ev.x;
    o.y = xv.y + g * ev.y;
    o.z = xv.z + g * ev.z;
    o.w = xv.w + g * ev.w;
    *(float4*)&out[e] = o;
}

// ---------------- launch ----------------------------------------------------------
extern "C" void kernel_launch(void* const* d_in, const int* in_sizes, int n_in,
                              void* d_out, int out_size) {
    const float* x       = (const float*)d_in[0];
    const float* w_embed = (const float*)d_in[1];
    const float* b_embed = (const float*)d_in[2];
    const float* bn1_g   = (const float*)d_in[3];
    const float* bn1_b   = (const float*)d_in[4];
    const float* bn1_m   = (const float*)d_in[5];
    const float* bn1_v   = (const float*)d_in[6];
    const float* w_enh   = (const float*)d_in[7];
    const float* b_enh   = (const float*)d_in[8];
    const float* bn2_g   = (const float*)d_in[9];
    const float* bn2_b   = (const float*)d_in[10];
    const float* bn2_m   = (const float*)d_in[11];
    const float* bn2_v   = (const float*)d_in[12];
    const float* w_g1    = (const float*)d_in[13];
    const float* b_g1    = (const float*)d_in[14];
    const float* w_g2    = (const float*)d_in[15];
    const float* b_g2    = (const float*)d_in[16];
    float* out = (float*)d_out;

    fold_kernel<<<256, 256>>>(w_embed, b_embed, bn1_g, bn1_b, bn1_m, bn1_v, 256, 0);
    fold_kernel<<<256, 256>>>(w_enh,   b_enh,   bn2_g, bn2_b, bn2_m, bn2_v, 512, 1);

    mma_gemm<256, 0><<<dim3(32, 2, Bq), 256>>>(x);              // fe
    norm1_kernel<<<512, 256>>>();
    norm2_kernel<<<128, 256>>>();
    simagg_kernel<<<dim3(Ww / TILE, Hh / TILE, Bq), 256>>>(x);  // agg
    mma_gemm<512, 1><<<dim3(32, 2, Bq), 256>>>(x);              // enhanced

    pool_kernel<<<dim3(512, Bq), 256>>>(x);
    gate_kernel<<<Bq, 256>>>(w_g1, b_g1, w_g2, b_g2);
    final_kernel<<<(unsigned)(TOTAL / 4 / 256), 256>>>(x, out);
}

// round 4
// speedup vs baseline: 1.9320x; 1.0788x over previous
#include <cuda_runtime.h>
#include <cstdint>
#include <cstddef>

#define Bq   8
#define Cc   256
#define Hh   64
#define Ww   64
#define HWc  4096
#define TOTAL (8UL*256*4096)

// ---------------- scratch (device globals) ------------------------------------
__device__ float g_fe  [TOTAL];
__device__ float g_agg [TOTAL];
__device__ float g_enh [TOTAL];
__device__ float g_w1f [256*256];
__device__ float g_w2f [256*512];
__device__ float g_b1f [256];
__device__ float g_b2f [256];
__device__ float g_nrm [Bq*HWc];
__device__ float g_poolp[Bq*32*256];   // per-(b, n-block) channel partials of enhanced
__device__ float g_pool[Bq*512];
__device__ float g_gate[Bq*256];

// ---------------- BN fold ------------------------------------------------------
__global__ void fold_kernel(const float* __restrict__ w, const float* __restrict__ bsrc,
                            const float* __restrict__ gm, const float* __restrict__ bt,
                            const float* __restrict__ mn, const float* __restrict__ vr,
                            int cin, int which) {
    int o = blockIdx.x;
    float inv = gm[o] * rsqrtf(vr[o] + 1e-5f);
    float* wf = which ? g_w2f : g_w1f;
    float* bf = which ? g_b2f : g_b1f;
    for (int c = threadIdx.x; c < cin; c += blockDim.x)
        wf[o * cin + c] = inv * w[o * cin + c];
    if (threadIdx.x == 0)
        bf[o] = bsrc[o] * inv + bt[o] - mn[o] * inv;
}

// ---------------- mma.sync tf32 GEMM: CTA 256x128, warp 64x64 ------------------
// out[b, m, n] = relu( sum_k A[m,k]*B[k,n] + bias[m] )
// PHASE 0: also emits per-pixel L2 norm over all 256 channels  -> g_nrm
// PHASE 1: also emits per-CTA channel row sums (pool partials) -> g_poolp
#define BK   16
#define PADA 20
#define PADB 136
#define SM_A  (2 * 256 * PADA)            // floats
#define SM_B  (2 * BK * PADB)
#define GSMEM ((SM_A + SM_B) * 4)         // bytes = 58368

__device__ __forceinline__ void mma_tf32(float c[4], const uint32_t a[4], const uint32_t b[2]) {
    asm volatile(
        "mma.sync.aligned.m16n8k8.row.col.f32.tf32.tf32.f32 "
        "{%0,%1,%2,%3}, {%4,%5,%6,%7}, {%8,%9}, {%0,%1,%2,%3};"
        : "+f"(c[0]), "+f"(c[1]), "+f"(c[2]), "+f"(c[3])
        : "r"(a[0]), "r"(a[1]), "r"(a[2]), "r"(a[3]), "r"(b[0]), "r"(b[1]));
}

template <int CIN, int PHASE>
__global__ __launch_bounds__(256) void mma_gemm(const float* __restrict__ xin) {
    extern __shared__ float dsm[];
    float* sA = dsm;
    float* sB = dsm + SM_A;
    float* sred = sB;                  // alias, used only after all MMA work

    const int tid  = threadIdx.x;
    const int wid  = tid >> 5;
    const int lane = tid & 31;
    const int wm = wid >> 1;           // 0..3
    const int wn = wid & 1;            // 0..1
    const int gq = lane >> 2;          // 0..7
    const int tg = lane & 3;           // 0..3

    const int bb = blockIdx.y;
    const int n0 = blockIdx.x * 128;

    const float* Aw   = PHASE ? g_w2f : g_w1f;
    const float* bias = PHASE ? g_b2f : g_b1f;
    float*       out  = PHASE ? g_enh : g_fe;
    const float* xb   = xin   + (size_t)bb * Cc * HWc;
    const float* aggb = g_agg + (size_t)bb * Cc * HWc;

    uint32_t sAa, sBa;
    asm("{ .reg .u64 t; cvta.to.shared.u64 t, %1; cvt.u32.u64 %0, t; }" : "=r"(sAa) : "l"(sA));
    asm("{ .reg .u64 t; cvta.to.shared.u64 t, %1; cvt.u32.u64 %0, t; }" : "=r"(sBa) : "l"(sB));

    auto fill = [&](int ci) {
        const int buf = ci & 1;
        const int k0 = ci * BK;
        const uint32_t sAb = sAa + buf * (256 * PADA * 4);
        const uint32_t sBb = sBa + buf * (BK * PADB * 4);
#pragma unroll
        for (int it = 0; it < 4; it++) {           // A: 256x16 = 1024 x 16B
            int id = it * 256 + tid;
            int r = id >> 2, q = id & 3;
            const float* gp = &Aw[(size_t)r * CIN + k0 + q * 4];
            uint32_t s = sAb + (uint32_t)(r * PADA + q * 4) * 4;
            asm volatile("cp.async.cg.shared.global [%0], [%1], 16;" :: "r"(s), "l"(gp));
        }
#pragma unroll
        for (int it = 0; it < 2; it++) {           // B: 16x128 = 512 x 16B
            int id = it * 256 + tid;
            int kr = id >> 5, q = id & 31;
            int kg = k0 + kr;
            const float* brow;
            if (PHASE == 0) brow = xb + (size_t)kg * HWc;
            else            brow = (kg < Cc) ? xb + (size_t)kg * HWc
                                             : aggb + (size_t)(kg - Cc) * HWc;
            const float* gp = &brow[n0 + q * 4];
            uint32_t s = sBb + (uint32_t)(kr * PADB + q * 4) * 4;
            asm volatile("cp.async.cg.shared.global [%0], [%1], 16;" :: "r"(s), "l"(gp));
        }
        asm volatile("cp.async.commit_group;" ::: "memory");
    };

    float acc[4][8][4];
#pragma unroll
    for (int mt = 0; mt < 4; mt++)
#pragma unroll
        for (int nt = 0; nt < 8; nt++)
#pragma unroll
            for (int i = 0; i < 4; i++) acc[mt][nt][i] = 0.f;

    constexpr int NC = CIN / BK;
    fill(0);

    for (int ci = 0; ci < NC; ci++) {
        if (ci + 1 < NC) {
            fill(ci + 1);
            asm volatile("cp.async.wait_group 1;" ::: "memory");
        } else {
            asm volatile("cp.async.wait_group 0;" ::: "memory");
        }
        __syncthreads();

        const int buf = ci & 1;
        const float* A_ = sA + buf * (256 * PADA);
        const float* B_ = sB + buf * (BK * PADB);
#pragma unroll
        for (int k8 = 0; k8 < 2; k8++) {
            const int kb = k8 * 8;
            uint32_t afr[4][4];
#pragma unroll
            for (int mt = 0; mt < 4; mt++) {
                int row = wm * 64 + mt * 16 + gq;
                afr[mt][0] = __float_as_uint(A_[row * PADA + kb + tg]);
                afr[mt][1] = __float_as_uint(A_[(row + 8) * PADA + kb + tg]);
                afr[mt][2] = __float_as_uint(A_[row * PADA + kb + tg + 4]);
                afr[mt][3] = __float_as_uint(A_[(row + 8) * PADA + kb + tg + 4]);
            }
            uint32_t bfr[8][2];
#pragma unroll
            for (int nt = 0; nt < 8; nt++) {
                int col = wn * 64 + nt * 8 + gq;
                bfr[nt][0] = __float_as_uint(B_[(kb + tg) * PADB + col]);
                bfr[nt][1] = __float_as_uint(B_[(kb + 4 + tg) * PADB + col]);
            }
#pragma unroll
            for (int mt = 0; mt < 4; mt++)
#pragma unroll
                for (int nt = 0; nt < 8; nt++)
                    mma_tf32(acc[mt][nt], afr[mt], bfr[nt]);
        }
        __syncthreads();
    }

    // ---------------- epilogue: bias + relu + store + fused reduction ----------
    float ssq[8][2];    // PHASE 0: per nt, per col-in-pair sum of squares over m
    float prt[4][2];    // PHASE 1: per mt, row sums over this warp's 64 cols
    if (PHASE == 0) {
#pragma unroll
        for (int nt = 0; nt < 8; nt++) { ssq[nt][0] = 0.f; ssq[nt][1] = 0.f; }
    } else {
#pragma unroll
        for (int mt = 0; mt < 4; mt++) { prt[mt][0] = 0.f; prt[mt][1] = 0.f; }
    }

#pragma unroll
    for (int mt = 0; mt < 4; mt++) {
        int row0 = wm * 64 + mt * 16 + gq;
        float bs0 = bias[row0];
        float bs1 = bias[row0 + 8];
        float* o0 = out + ((size_t)bb * Cc + row0) * HWc + n0;
        float* o1 = o0 + 8 * HWc;
#pragma unroll
        for (int nt = 0; nt < 8; nt++) {
            int col = wn * 64 + nt * 8 + 2 * tg;
            float v0x = fmaxf(acc[mt][nt][0] + bs0, 0.f);
            float v0y = fmaxf(acc[mt][nt][1] + bs0, 0.f);
            float v1x = fmaxf(acc[mt][nt][2] + bs1, 0.f);
            float v1y = fmaxf(acc[mt][nt][3] + bs1, 0.f);
            float2 a = {v0x, v0y}, b2 = {v1x, v1y};
            *(float2*)&o0[col] = a;
            *(float2*)&o1[col] = b2;
            if (PHASE == 0) {
                ssq[nt][0] += v0x * v0x + v1x * v1x;
                ssq[nt][1] += v0y * v0y + v1y * v1y;
            } else {
                prt[mt][0] += v0x + v0y;
                prt[mt][1] += v1x + v1y;
            }
        }
    }

    if (PHASE == 0) {
        // reduce over gq (lanes tg, tg+4, ..., tg+28)
#pragma unroll
        for (int nt = 0; nt < 8; nt++) {
#pragma unroll
            for (int off = 16; off >= 4; off >>= 1) {
                ssq[nt][0] += __shfl_down_sync(0xffffffffu, ssq[nt][0], off);
                ssq[nt][1] += __shfl_down_sync(0xffffffffu, ssq[nt][1], off);
            }
        }
        if (lane < 4) {
#pragma unroll
            for (int nt = 0; nt < 8; nt++) {
                int col = wn * 64 + nt * 8 + 2 * tg;
                sred[wm * 128 + col]     = ssq[nt][0];
                sred[wm * 128 + col + 1] = ssq[nt][1];
            }
        }
        __syncthreads();
        if (tid < 128) {
            float s = sred[tid] + sred[128 + tid] + sred[256 + tid] + sred[384 + tid];
            g_nrm[bb * HWc + n0 + tid] = sqrtf(s);
        }
    } else {
        // reduce over tg (4 adjacent lanes)
#pragma unroll
        for (int mt = 0; mt < 4; mt++) {
            prt[mt][0] += __shfl_down_sync(0xffffffffu, prt[mt][0], 2);
            prt[mt][0] += __shfl_down_sync(0xffffffffu, prt[mt][0], 1);
            prt[mt][1] += __shfl_down_sync(0xffffffffu, prt[mt][1], 2);
            prt[mt][1] += __shfl_down_sync(0xffffffffu, prt[mt][1], 1);
        }
        if (tg == 0) {
#pragma unroll
            for (int mt = 0; mt < 4; mt++) {
                int row0 = wm * 64 + mt * 16 + gq;
                sred[wn * 256 + row0]     = prt[mt][0];
                sred[wn * 256 + row0 + 8] = prt[mt][1];
            }
        }
        __syncthreads();
        if (tid < 256)
            g_poolp[((size_t)bb * 32 + blockIdx.x) * 256 + tid] =
                sred[tid] + sred[256 + tid];
    }
}

// ---------------- cosine sim + softmax + aggregation (transposed smem) ---------
#define TILE 16
#define HALO 18
#define NPIX (HALO * HALO)    // 324
#define CKC  16
#define SHSTR 20              // floats per pixel row (16 ch + 4 pad)
__global__ __launch_bounds__(256) void simagg_kernel(const float* __restrict__ xin) {
    __shared__ float sh[NPIX * SHSTR];    // 25920 B

    const int b  = blockIdx.z;
    const int h0 = blockIdx.y * TILE;
    const int w0 = blockIdx.x * TILE;
    const int lx = threadIdx.x & (TILE - 1);
    const int ly = threadIdx.x / TILE;
    const int h = h0 + ly, w = w0 + lx;
    const int pc = ly * HALO + lx;        // halo index of (h-1, w-1)

    const float* feb = g_fe + (size_t)b * Cc * HWc;
    const float* xb  = xin  + (size_t)b * Cc * HWc;

    float4 dot4[9];
#pragma unroll
    for (int k = 0; k < 9; k++) dot4[k] = make_float4(0.f, 0.f, 0.f, 0.f);

    // ---- pass 1: 9 cosine dots over all channels
    for (int cc = 0; cc < Cc; cc += CKC) {
        for (int idx = threadIdx.x; idx < CKC * NPIX; idx += 256) {
            int c = idx / NPIX;
            int p = idx - c * NPIX;
            int hy = p / HALO, hx = p - hy * HALO;
            int gh = h0 + hy - 1, gw = w0 + hx - 1;
            float v = 0.f;
            if (gh >= 0 && gh < Hh && gw >= 0 && gw < Ww)
                v = feb[(size_t)(cc + c) * HWc + gh * Ww + gw];
            sh[p * SHSTR + c] = v;
        }
        __syncthreads();
#pragma unroll
        for (int c4 = 0; c4 < 4; c4++) {
            float4 ctr = *(const float4*)&sh[(pc + HALO + 1) * SHSTR + c4 * 4];
#pragma unroll
            for (int di = 0; di < 3; di++)
#pragma unroll
                for (int dj = 0; dj < 3; dj++) {
                    float4 nb = *(const float4*)&sh[(pc + di * HALO + dj) * SHSTR + c4 * 4];
                    int k = di * 3 + dj;
                    dot4[k].x += ctr.x * nb.x;
                    dot4[k].y += ctr.y * nb.y;
                    dot4[k].z += ctr.z * nb.z;
                    dot4[k].w += ctr.w * nb.w;
                }
        }
        __syncthreads();
    }

    // ---- cosine + softmax over the 9-window
    float nc = g_nrm[b * HWc + h * Ww + w];
    float s[9];
#pragma unroll
    for (int k = 0; k < 9; k++) {
        int di = k / 3, dj = k - 3 * di;
        int nh = h + di - 1, nw = w + dj - 1;
        float np = (nh >= 0 && nh < Hh && nw >= 0 && nw < Ww)
                       ? g_nrm[b * HWc + nh * Ww + nw] : 0.f;
        float d = dot4[k].x + dot4[k].y + dot4[k].z + dot4[k].w;
        s[k] = d / (nc * np + 1e-7f);
    }
    float mx = s[0];
#pragma unroll
    for (int k = 1; k < 9; k++) mx = fmaxf(mx, s[k]);
    float sum = 0.f;
#pragma unroll
    for (int k = 0; k < 9; k++) { s[k] = expf(s[k] - mx); sum += s[k]; }
    float inv = 1.f / sum;
#pragma unroll
    for (int k = 0; k < 9; k++) s[k] *= inv;

    // ---- pass 2: weighted 3x3 gather on x
    float* aggb = g_agg + (size_t)b * Cc * HWc;
    for (int cc = 0; cc < Cc; cc += CKC) {
        for (int idx = threadIdx.x; idx < CKC * NPIX; idx += 256) {
            int c = idx / NPIX;
            int p = idx - c * NPIX;
            int hy = p / HALO, hx = p - hy * HALO;
            int gh = h0 + hy - 1, gw = w0 + hx - 1;
            float v = 0.f;
            if (gh >= 0 && gh < Hh && gw >= 0 && gw < Ww)
                v = xb[(size_t)(cc + c) * HWc + gh * Ww + gw];
            sh[p * SHSTR + c] = v;
        }
        __syncthreads();
#pragma unroll
        for (int c4 = 0; c4 < 4; c4++) {
            float4 a = make_float4(0.f, 0.f, 0.f, 0.f);
#pragma unroll
            for (int di = 0; di < 3; di++)
#pragma unroll
                for (int dj = 0; dj < 3; dj++) {
                    float4 nb = *(const float4*)&sh[(pc + di * HALO + dj) * SHSTR + c4 * 4];
                    float wk = s[di * 3 + dj];
                    a.x += wk * nb.x;
                    a.y += wk * nb.y;
                    a.z += wk * nb.z;
                    a.w += wk * nb.w;
                }
            size_t base = (size_t)(cc + c4 * 4) * HWc + h * Ww + w;
            aggb[base]            = a.x;
            aggb[base + HWc]      = a.y;
            aggb[base + 2 * HWc]  = a.z;
            aggb[base + 3 * HWc]  = a.w;
        }
        __syncthreads();
    }
}

// ---------------- pool of x (channels 0..255 of the concat) --------------------
__global__ void poolx_kernel(const float* __restrict__ xin) {
    const int c = blockIdx.x;
    const int b = blockIdx.y;
    const int tid = threadIdx.x;
    const float* src = xin + ((size_t)b * Cc + c) * HWc;
    float s = 0.f;
#pragma unroll
    for (int i = tid * 4; i < HWc; i += 1024) {
        float4 v = *(const float4*)&src[i];
        s += v.x + v.y + v.z + v.w;
    }
#pragma unroll
    for (int o = 16; o > 0; o >>= 1) s += __shfl_down_sync(0xffffffffu, s, o);
    __shared__ float red[8];
    if ((tid & 31) == 0) red[tid >> 5] = s;
    __syncthreads();
    if (tid < 8) {
        float t = red[tid];
#pragma unroll
        for (int o = 4; o > 0; o >>= 1) t += __shfl_down_sync(0xffu, t, o);
        if (tid == 0) g_pool[b * 512 + c] = t * (1.f / HWc);
    }
}

// ---------------- combine enhanced pool partials -------------------------------
__global__ void pool2_kernel() {
    const int b = blockIdx.x;
    const int c = threadIdx.x;
    float s = 0.f;
#pragma unroll 8
    for (int nb = 0; nb < 32; nb++)
        s += g_poolp[((size_t)b * 32 + nb) * 256 + c];
    g_pool[b * 512 + 256 + c] = s * (1.f / HWc);
}

// ---------------- SE gate --------------------------------------------------------
__global__ void gate_kernel(const float* __restrict__ w1, const float* __restrict__ b1,
                            const float* __restrict__ w2, const float* __restrict__ b2) {
    const int b = blockIdx.x;
    const int tid = threadIdx.x;
    __shared__ float sp[512];
    __shared__ float shid[64];
    for (int i = tid; i < 512; i += 256) sp[i] = g_pool[b * 512 + i];
    __syncthreads();
    if (tid < 64) {
        float s = b1[tid];
        const float* wr = w1 + tid * 512;
#pragma unroll 8
        for (int c = 0; c < 512; c++) s += wr[c] * sp[c];
        shid[tid] = fmaxf(s, 0.f);
    }
    __syncthreads();
    float s = b2[tid];
    const float* wr = w2 + tid * 64;
#pragma unroll
    for (int j = 0; j < 64; j++) s += wr[j] * shid[j];
    g_gate[b * 256 + tid] = 1.f / (1.f + expf(-s));
}

// ---------------- residual + gated enhancement ----------------------------------
__global__ void final_kernel(const float* __restrict__ xin, float* __restrict__ out) {
    size_t e = ((size_t)blockIdx.x * blockDim.x + threadIdx.x) * 4;
    if (e >= TOTAL) return;
    int bc = (int)(e >> 12);
    float g = g_gate[bc];
    float4 xv = *(const float4*)&xin[e];
    float4 ev = *(const float4*)&g_enh[e];
    float4 o;
    o.x = xv.x + g * ev.x;
    o.y = xv.y + g * ev.y;
    o.z = xv.z + g * ev.z;
    o.w = xv.w + g * ev.w;
    *(float4*)&out[e] = o;
}

// ---------------- launch ----------------------------------------------------------
extern "C" void kernel_launch(void* const* d_in, const int* in_sizes, int n_in,
                              void* d_out, int out_size) {
    const float* x       = (const float*)d_in[0];
    const float* w_embed = (const float*)d_in[1];
    const float* b_embed = (const float*)d_in[2];
    const float* bn1_g   = (const float*)d_in[3];
    const float* bn1_b   = (const float*)d_in[4];
    const float* bn1_m   = (const float*)d_in[5];
    const float* bn1_v   = (const float*)d_in[6];
    const float* w_enh   = (const float*)d_in[7];
    const float* b_enh   = (const float*)d_in[8];
    const float* bn2_g   = (const float*)d_in[9];
    const float* bn2_b   = (const float*)d_in[10];
    const float* bn2_m   = (const float*)d_in[11];
    const float* bn2_v   = (const float*)d_in[12];
    const float* w_g1    = (const float*)d_in[13];
    const float* b_g1    = (const float*)d_in[14];
    const float* w_g2    = (const float*)d_in[15];
    const float* b_g2    = (const float*)d_in[16];
    float* out = (float*)d_out;

    static bool attr_done = false;
    if (!attr_done) {
        cudaFuncSetAttribute(mma_gemm<256, 0>, cudaFuncAttributeMaxDynamicSharedMemorySize, GSMEM);
        cudaFuncSetAttribute(mma_gemm<512, 1>, cudaFuncAttributeMaxDynamicSharedMemorySize, GSMEM);
        attr_done = true;
    }

    fold_kernel<<<256, 256>>>(w_embed, b_embed, bn1_g, bn1_b, bn1_m, bn1_v, 256, 0);
    fold_kernel<<<256, 256>>>(w_enh,   b_enh,   bn2_g, bn2_b, bn2_m, bn2_v, 512, 1);
    poolx_kernel<<<dim3(256, Bq), 256>>>(x);                      // independent

    mma_gemm<256, 0><<<dim3(32, Bq), 256, GSMEM>>>(x);            // fe + norm (4th: profiled)
    simagg_kernel<<<dim3(Ww / TILE, Hh / TILE, Bq), 256>>>(x);    // agg
    mma_gemm<512, 1><<<dim3(32, Bq), 256, GSMEM>>>(x);            // enhanced + pool partials

    pool2_kernel<<<Bq, 256>>>();
    gate_kernel<<<Bq, 256>>>(w_g1, b_g1, w_g2, b_g2);
    final_kernel<<<(unsigned)(TOTAL / 4 / 256), 256>>>(x, out);
}